// round 8
// baseline (speedup 1.0000x reference)
#include <cuda_runtime.h>
#include <cstdint>

#define Bq 4
#define T 128
#define D 300
#define D4 75            // D / 4 (float4 count per row)

// Scratch for projected q (rows 0..511), k (512..1023), v (1024..1535)
__device__ __align__(16) float g_qkv[3 * Bq * T * D];

// ---- cp.async helpers (per-thread group state) ------------------------------
__device__ __forceinline__ uint32_t smem_u32(const void* p) {
    return (uint32_t)__cvta_generic_to_shared(p);
}
#define CP_ASYNC16(dst_u32, src_ptr) \
    asm volatile("cp.async.cg.shared.global [%0], [%1], 16;" \
                 :: "r"(dst_u32), "l"(src_ptr) : "memory")
#define CP_COMMIT() asm volatile("cp.async.commit_group;" ::: "memory")
#define CP_WAIT1()  asm volatile("cp.async.wait_group 1;" ::: "memory")
#define CP_WAIT0()  asm volatile("cp.async.wait_group 0;" ::: "memory")

// ---------------------------------------------------------------------------
// Kernel 1: batched projection GEMM (round-5 winner, unchanged).
// 32x64 tiles, 128 threads, 4x4 microtile, k-chunk 32, double-buffered.
// ---------------------------------------------------------------------------
__global__ __launch_bounds__(128) void proj_kernel(
    const float* __restrict__ query, const float* __restrict__ key,
    const float* __restrict__ value,
    const float* __restrict__ WQ, const float* __restrict__ bQ,
    const float* __restrict__ WK, const float* __restrict__ bK)
{
    __shared__ float A_s[2][32][36];
    __shared__ float W_s[2][32][68];

    const int row0 = blockIdx.y * 32;
    const int col0 = blockIdx.x * 64;
    const int tid  = threadIdx.x;
    const int tx   = tid & 15;
    const int ty   = tid >> 4;

    const int sel = row0 >> 9;
    const float* Ap = (sel == 0) ? query : (sel == 1 ? key : value);
    const float* Wp = (sel == 0) ? WQ : WK;
    const float* bp = (sel == 0) ? bQ : bK;
    const int arow0 = row0 & 511;

    const int NC = (D + 31) / 32;
    float4 a_r[2], w_r[4];

    auto fetch = [&](int k0) {
#pragma unroll
        for (int p = 0; p < 2; p++) {
            int idx = p * 128 + tid;
            int ar = idx & 31, kk = k0 + ((idx >> 5) << 2);
            a_r[p] = (kk < D) ? *(const float4*)&Ap[(arow0 + ar) * D + kk]
                              : make_float4(0.f, 0.f, 0.f, 0.f);
        }
#pragma unroll
        for (int p = 0; p < 4; p++) {
            int idx = p * 128 + tid;
            int wr = idx & 63, kk = k0 + ((idx >> 6) << 2);
            int gc = col0 + wr;
            w_r[p] = (kk < D && gc < D) ? *(const float4*)&Wp[gc * D + kk]
                                        : make_float4(0.f, 0.f, 0.f, 0.f);
        }
    };
    auto store = [&](int buf) {
#pragma unroll
        for (int p = 0; p < 2; p++) {
            int idx = p * 128 + tid;
            int ar = idx & 31, e = (idx >> 5) << 2;
            A_s[buf][e + 0][ar] = a_r[p].x; A_s[buf][e + 1][ar] = a_r[p].y;
            A_s[buf][e + 2][ar] = a_r[p].z; A_s[buf][e + 3][ar] = a_r[p].w;
        }
#pragma unroll
        for (int p = 0; p < 4; p++) {
            int idx = p * 128 + tid;
            int wr = idx & 63, e = (idx >> 6) << 2;
            W_s[buf][e + 0][wr] = w_r[p].x; W_s[buf][e + 1][wr] = w_r[p].y;
            W_s[buf][e + 2][wr] = w_r[p].z; W_s[buf][e + 3][wr] = w_r[p].w;
        }
    };

    float acc[4][4];
#pragma unroll
    for (int r = 0; r < 4; r++)
#pragma unroll
        for (int c = 0; c < 4; c++) acc[r][c] = 0.f;

    fetch(0);
    store(0);
    __syncthreads();

    for (int ch = 0; ch < NC; ch++) {
        const int buf = ch & 1;
        if (ch + 1 < NC) fetch((ch + 1) * 32);
#pragma unroll
        for (int e = 0; e < 32; e++) {
            float4 av = *(const float4*)&A_s[buf][e][ty * 4];
            float4 wv = *(const float4*)&W_s[buf][e][tx * 4];
            float a4[4] = {av.x, av.y, av.z, av.w};
            float w4[4] = {wv.x, wv.y, wv.z, wv.w};
#pragma unroll
            for (int r = 0; r < 4; r++)
#pragma unroll
                for (int c = 0; c < 4; c++) acc[r][c] += a4[r] * w4[c];
        }
        if (ch + 1 < NC) store(1 - buf);
        __syncthreads();
    }

#pragma unroll
    for (int r = 0; r < 4; r++) {
        int gr = row0 + ty * 4 + r;
#pragma unroll
        for (int c = 0; c < 4; c++) {
            int gcol = col0 + tx * 4 + c;
            if (gcol < D) g_qkv[gr * D + gcol] = acc[r][c] + bp[gcol];
        }
    }
}

// ---------------------------------------------------------------------------
// Kernel 2: fused attention. One CTA per (b, i), 128 threads (4 warps),
// 4 CTAs/SM (single wave). Each warp runs a PRIVATE 3-stage cp.async
// pipeline over its 32 j-rows (no barriers in the mainloop): stage s =
// {hL_j, hR_j, k_j} rows (3.6KB) into its own SMEM slab. cp.async groups
// are per-thread, so warps proceed independently with 2 stages in flight.
// ---------------------------------------------------------------------------
__global__ __launch_bounds__(128, 4) void attn_kernel(
    const float* __restrict__ hL, const float* __restrict__ hR,
    float* __restrict__ out)
{
    __shared__ float4 buf_s[4][3][225];   // [warp][stage][idx: 0-74 hL,75-149 hR,150-224 k]
    __shared__ float  q_s[304];
    __shared__ float  scores_s[128];
    __shared__ float  attn_s[128];

    const int tid  = threadIdx.x;
    const int lane = tid & 31;
    const int w    = tid >> 5;           // 4 warps
    const int b    = blockIdx.x >> 7;
    const int i    = blockIdx.x & 127;

    const float4* qkv4 = (const float4*)g_qkv;
    const float4* hL4  = (const float4*)hL + (size_t)(b * T + i) * T * D4;
    const float4* hRb  = (const float4*)hR + ((size_t)b * T * T + i) * D4;
    const float4* k4b  = qkv4 + (Bq * T + b * T) * D4;

    // ---- load q_i (L2-hot) ----
    if (tid < D4) ((float4*)q_s)[tid] = qkv4[(b * T + i) * D4 + tid];
    __syncthreads();

    const float4* q4 = (const float4*)q_s;
    const int j0 = w * 32;               // this warp's j range: [j0, j0+32)

    // per-stage async issue: 225 float4 into this warp's slab
    auto issue = [&](int s) {
        const int j = j0 + s;
        const float4* hl = hL4 + (size_t)j * D4;
        const float4* hr = hRb + (size_t)j * T * D4;
        const float4* kp = k4b + j * D4;
        float4* slab = &buf_s[w][s % 3][0];
#pragma unroll
        for (int p = 0; p < 8; p++) {
            int idx = p * 32 + lane;
            if (idx < 225) {
                const float4* src;
                if (idx < 75)       src = hl + idx;
                else if (idx < 150) src = hr + (idx - 75);
                else                src = kp + (idx - 150);
                CP_ASYNC16(smem_u32(slab + idx), src);
            }
        }
    };

    issue(0); CP_COMMIT();
    issue(1); CP_COMMIT();

    for (int s = 0; s < 32; s++) {
        if (s < 31) { CP_WAIT1(); } else { CP_WAIT0(); }
        __syncwarp();

        const float4* S = &buf_s[w][s % 3][0];

        // first 2 chunks (always valid: c < 64 <= 75)
        int c0 = lane, c1 = lane + 32;
        float4 l0 = S[c0], r0 = S[75 + c0], k0 = S[150 + c0], qq0 = q4[c0];
        float4 l1 = S[c1], r1 = S[75 + c1], k1 = S[150 + c1], qq1 = q4[c1];
        float acc = (qq0.x + l0.x) * (k0.x + r0.x) + (qq0.y + l0.y) * (k0.y + r0.y)
                  + (qq0.z + l0.z) * (k0.z + r0.z) + (qq0.w + l0.w) * (k0.w + r0.w)
                  + (qq1.x + l1.x) * (k1.x + r1.x) + (qq1.y + l1.y) * (k1.y + r1.y)
                  + (qq1.z + l1.z) * (k1.z + r1.z) + (qq1.w + l1.w) * (k1.w + r1.w);
        if (lane < D4 - 64) {            // c2 = 64..74
            int c2 = lane + 64;
            float4 l2 = S[c2], r2 = S[75 + c2], k2 = S[150 + c2], qq2 = q4[c2];
            acc += (qq2.x + l2.x) * (k2.x + r2.x) + (qq2.y + l2.y) * (k2.y + r2.y)
                 + (qq2.z + l2.z) * (k2.z + r2.z) + (qq2.w + l2.w) * (k2.w + r2.w);
        }

        // keep the pipeline fed BEFORE the shuffle chain
        if (s + 2 < 32) issue(s + 2);
        CP_COMMIT();   // empty group on tail keeps wait_group semantics

#pragma unroll
        for (int o = 16; o > 0; o >>= 1)
            acc += __shfl_xor_sync(0xffffffffu, acc, o);
        if (lane == 0) scores_s[j0 + s] = acc;
    }
    __syncthreads();

    // ---- p = softmax(scores); attn = softmax(1000*p); clip is a no-op.
    // p_max = 1/sum exactly (max exp term is 1): 1000*(p-p_max) = 1000*inv*(e-1)
    if (w == 0) {
        float s0 = scores_s[lane],      s1 = scores_s[lane + 32];
        float s2 = scores_s[lane + 64], s3 = scores_s[lane + 96];
        float m = fmaxf(fmaxf(s0, s1), fmaxf(s2, s3));
#pragma unroll
        for (int o = 16; o > 0; o >>= 1)
            m = fmaxf(m, __shfl_xor_sync(0xffffffffu, m, o));
        float e0 = expf(s0 - m), e1 = expf(s1 - m);
        float e2 = expf(s2 - m), e3 = expf(s3 - m);
        float sum = e0 + e1 + e2 + e3;
#pragma unroll
        for (int o = 16; o > 0; o >>= 1)
            sum += __shfl_xor_sync(0xffffffffu, sum, o);
        float inv = 1.f / sum;
        float a0 = expf(1000.f * inv * (e0 - 1.f));
        float a1 = expf(1000.f * inv * (e1 - 1.f));
        float a2 = expf(1000.f * inv * (e2 - 1.f));
        float a3 = expf(1000.f * inv * (e3 - 1.f));
        float sum2 = a0 + a1 + a2 + a3;
#pragma unroll
        for (int o = 16; o > 0; o >>= 1)
            sum2 += __shfl_xor_sync(0xffffffffu, sum2, o);
        float inv2 = 1.f / sum2;
        attn_s[lane]      = a0 * inv2;
        attn_s[lane + 32] = a1 * inv2;
        attn_s[lane + 64] = a2 * inv2;
        attn_s[lane + 96] = a3 * inv2;
    }
    __syncthreads();

    // ---- output: out[b,i,d] = sum_j attn_j * (v[b,j,d] + hR[b,j,i,d])
    // attn is near-one-hot after x1000 sharpening: skip negligible j.
    const float* vg  = g_qkv + (size_t)(2 * Bq * T + b * T) * D;
    const float* hRs = hR + ((size_t)b * T * T + i) * D;
#pragma unroll
    for (int rep = 0; rep < 3; rep++) {
        int d = tid + rep * 128;
        if (d < D) {
            float acc = 0.f;
            for (int j = 0; j < T; j++) {
                float a = attn_s[j];
                if (a > 1e-12f)
                    acc += a * (vg[j * D + d] + hRs[(size_t)j * T * D + d]);
            }
            out[(b * T + i) * D + d] = acc;
        }
    }
}

// ---------------------------------------------------------------------------
extern "C" void kernel_launch(void* const* d_in, const int* in_sizes, int n_in,
                              void* d_out, int out_size)
{
    const float* query = (const float*)d_in[0];
    const float* key   = (const float*)d_in[1];
    const float* value = (const float*)d_in[2];
    const float* hL    = (const float*)d_in[3];
    const float* hR    = (const float*)d_in[4];
    const float* WQ    = (const float*)d_in[5];
    const float* bQ    = (const float*)d_in[6];
    const float* WK    = (const float*)d_in[7];
    const float* bK    = (const float*)d_in[8];
    float* out = (float*)d_out;

    proj_kernel<<<dim3(5, 48), 128>>>(query, key, value, WQ, bQ, WK, bK);
    attn_kernel<<<Bq * T, 128>>>(hL, hR, out);
}

// round 9
// speedup vs baseline: 1.1833x; 1.1833x over previous
#include <cuda_runtime.h>
#include <cstdint>

#define Bq 4
#define T 128
#define D 300
#define D4 75            // D / 4 (float4 count per row)

// Scratch for projected q (rows 0..511), k (512..1023), v (1024..1535)
__device__ __align__(16) float g_qkv[3 * Bq * T * D];

// ---------------------------------------------------------------------------
// Kernel 1: batched projection GEMM — tuned for WARP COUNT, not per-thread
// work. 32x32 tiles, 128 threads, 4x2 microtile (8 outputs/thread), k-chunk
// 32, double-buffered. Grid (10, 48) = 480 CTAs = 1920 warps (~13/SM).
// out[r,c] = A[r,:] . W[c,:] + bias[c]
// rows 0..511 -> query/WQ/bQ, 512..1023 -> key/WK/bK, 1024..1535 -> value/WK/bK
// ---------------------------------------------------------------------------
__global__ __launch_bounds__(128) void proj_kernel(
    const float* __restrict__ query, const float* __restrict__ key,
    const float* __restrict__ value,
    const float* __restrict__ WQ, const float* __restrict__ bQ,
    const float* __restrict__ WK, const float* __restrict__ bK)
{
    __shared__ float A_s[2][32][36];   // float4 reads: stride 36 keeps 16B align
    __shared__ float W_s[2][32][34];   // float2 reads: stride 34 keeps 8B align

    const int row0 = blockIdx.y * 32;
    const int col0 = blockIdx.x * 32;
    const int tid  = threadIdx.x;
    const int tx   = tid & 15;    // 16 col groups x 2 cols
    const int ty   = tid >> 4;    // 8 row groups x 4 rows

    const int sel = row0 >> 9;    // 0: query, 1: key, 2: value
    const float* Ap = (sel == 0) ? query : (sel == 1 ? key : value);
    const float* Wp = (sel == 0) ? WQ : WK;
    const float* bp = (sel == 0) ? bQ : bK;
    const int arow0 = row0 & 511;

    // loader: 256 float4 per tile per chunk -> 2 per thread (A and W each)
    const int lm = tid >> 3;          // 0..15 -> two rows lm, lm+16
    const int lk = (tid & 7) * 4;     // k offset within chunk

    const int NC = (D + 31) / 32;     // 10 chunks
    float4 a_r[2], w_r[2];

    auto fetch = [&](int k0) {
        bool kv = (k0 + lk) < D;      // D%4==0: float4 never straddles
#pragma unroll
        for (int p = 0; p < 2; p++) {
            int r = lm + p * 16;
            a_r[p] = kv ? *(const float4*)&Ap[(arow0 + r) * D + k0 + lk]
                        : make_float4(0.f, 0.f, 0.f, 0.f);
            int gc = col0 + r;
            w_r[p] = (kv && gc < D) ? *(const float4*)&Wp[gc * D + k0 + lk]
                                    : make_float4(0.f, 0.f, 0.f, 0.f);
        }
    };
    auto store = [&](int buf) {
#pragma unroll
        for (int p = 0; p < 2; p++) {
            int r = lm + p * 16;
            A_s[buf][lk + 0][r] = a_r[p].x; A_s[buf][lk + 1][r] = a_r[p].y;
            A_s[buf][lk + 2][r] = a_r[p].z; A_s[buf][lk + 3][r] = a_r[p].w;
            W_s[buf][lk + 0][r] = w_r[p].x; W_s[buf][lk + 1][r] = w_r[p].y;
            W_s[buf][lk + 2][r] = w_r[p].z; W_s[buf][lk + 3][r] = w_r[p].w;
        }
    };

    float acc[4][2];
#pragma unroll
    for (int r = 0; r < 4; r++) { acc[r][0] = 0.f; acc[r][1] = 0.f; }

    fetch(0);
    store(0);
    __syncthreads();

    for (int ch = 0; ch < NC; ch++) {
        const int buf = ch & 1;
        if (ch + 1 < NC) fetch((ch + 1) * 32);
#pragma unroll
        for (int e = 0; e < 32; e++) {
            float4 av = *(const float4*)&A_s[buf][e][ty * 4];
            float2 wv = *(const float2*)&W_s[buf][e][tx * 2];
            acc[0][0] += av.x * wv.x; acc[0][1] += av.x * wv.y;
            acc[1][0] += av.y * wv.x; acc[1][1] += av.y * wv.y;
            acc[2][0] += av.z * wv.x; acc[2][1] += av.z * wv.y;
            acc[3][0] += av.w * wv.x; acc[3][1] += av.w * wv.y;
        }
        if (ch + 1 < NC) store(1 - buf);
        __syncthreads();
    }

#pragma unroll
    for (int r = 0; r < 4; r++) {
        int gr = row0 + ty * 4 + r;
#pragma unroll
        for (int c = 0; c < 2; c++) {
            int gcol = col0 + tx * 2 + c;
            if (gcol < D) g_qkv[gr * D + gcol] = acc[r][c] + bp[gcol];
        }
    }
}

// ---------------------------------------------------------------------------
// Kernel 2: fused attention — EXACT round-4 winner (36.06us, DRAM 57%).
// One CTA per (b, i), 256 threads, 4 CTAs/SM (single wave), plain LDG
// streaming with 9 float4 in flight per warp per j.
// ---------------------------------------------------------------------------
__global__ __launch_bounds__(256, 4) void attn_kernel(
    const float* __restrict__ hL, const float* __restrict__ hR,
    float* __restrict__ out)
{
    __shared__ float q_s[304];
    __shared__ float scores_s[128];
    __shared__ float attn_s[128];

    const int tid  = threadIdx.x;
    const int lane = tid & 31;
    const int w    = tid >> 5;           // 8 warps
    const int b    = blockIdx.x >> 7;
    const int i    = blockIdx.x & 127;

    const float4* qkv4 = (const float4*)g_qkv;

    // ---- load q_i (L2-hot, tiny) ----
    if (tid < D4) ((float4*)q_s)[tid] = qkv4[(b * T + i) * D4 + tid];
    __syncthreads();

    const float4* q4 = (const float4*)q_s;
    const bool has_c = (lane < D4 - 64);           // lane < 11

    // ---- scoring: scores_j = sum_d (q[d]+hL[b,i,j,d]) * (k[b,j,d]+hR[b,j,i,d])
    const float4* hL4 = (const float4*)hL + (size_t)(b * T + i) * T * D4;
    const float4* hRb = (const float4*)hR + ((size_t)b * T * T + i) * D4;
    const float4* k4b = qkv4 + (Bq * T + b * T) * D4;

#pragma unroll 2
    for (int jj = 0; jj < 16; jj++) {
        const int j = w * 16 + jj;
        const float4* hl = hL4 + j * D4;
        const float4* hr = hRb + (size_t)j * T * D4;
        const float4* kp = k4b + j * D4;

        float4 l0 = hl[lane],      r0 = hr[lane],      k0 = kp[lane];
        float4 l1 = hl[lane + 32], r1 = hr[lane + 32], k1 = kp[lane + 32];
        float4 l2, r2, k2;
        if (has_c) { l2 = hl[lane + 64]; r2 = hr[lane + 64]; k2 = kp[lane + 64]; }

        float4 qa = q4[lane];
        float acc = (qa.x + l0.x) * (k0.x + r0.x) + (qa.y + l0.y) * (k0.y + r0.y)
                  + (qa.z + l0.z) * (k0.z + r0.z) + (qa.w + l0.w) * (k0.w + r0.w);
        float4 qb = q4[lane + 32];
        acc += (qb.x + l1.x) * (k1.x + r1.x) + (qb.y + l1.y) * (k1.y + r1.y)
             + (qb.z + l1.z) * (k1.z + r1.z) + (qb.w + l1.w) * (k1.w + r1.w);
        if (has_c) {
            float4 qc = q4[lane + 64];
            acc += (qc.x + l2.x) * (k2.x + r2.x) + (qc.y + l2.y) * (k2.y + r2.y)
                 + (qc.z + l2.z) * (k2.z + r2.z) + (qc.w + l2.w) * (k2.w + r2.w);
        }
#pragma unroll
        for (int o = 16; o > 0; o >>= 1)
            acc += __shfl_xor_sync(0xffffffffu, acc, o);
        if (lane == 0) scores_s[j] = acc;
    }
    __syncthreads();

    // ---- p = softmax(scores); attn = softmax(1000*p); clip is a no-op.
    // p_max = 1/sum exactly (max exp term is 1): 1000*(p-p_max) = 1000*inv*(e-1)
    if (w == 0) {
        float s0 = scores_s[lane],      s1 = scores_s[lane + 32];
        float s2 = scores_s[lane + 64], s3 = scores_s[lane + 96];
        float m = fmaxf(fmaxf(s0, s1), fmaxf(s2, s3));
#pragma unroll
        for (int o = 16; o > 0; o >>= 1)
            m = fmaxf(m, __shfl_xor_sync(0xffffffffu, m, o));
        float e0 = expf(s0 - m), e1 = expf(s1 - m);
        float e2 = expf(s2 - m), e3 = expf(s3 - m);
        float sum = e0 + e1 + e2 + e3;
#pragma unroll
        for (int o = 16; o > 0; o >>= 1)
            sum += __shfl_xor_sync(0xffffffffu, sum, o);
        float inv = 1.f / sum;
        float a0 = expf(1000.f * inv * (e0 - 1.f));
        float a1 = expf(1000.f * inv * (e1 - 1.f));
        float a2 = expf(1000.f * inv * (e2 - 1.f));
        float a3 = expf(1000.f * inv * (e3 - 1.f));
        float sum2 = a0 + a1 + a2 + a3;
#pragma unroll
        for (int o = 16; o > 0; o >>= 1)
            sum2 += __shfl_xor_sync(0xffffffffu, sum2, o);
        float inv2 = 1.f / sum2;
        attn_s[lane]      = a0 * inv2;
        attn_s[lane + 32] = a1 * inv2;
        attn_s[lane + 64] = a2 * inv2;
        attn_s[lane + 96] = a3 * inv2;
    }
    __syncthreads();

    // ---- output: out[b,i,d] = sum_j attn_j * (v[b,j,d] + hR[b,j,i,d])
    // attn is near-one-hot after x1000 sharpening: skip negligible j.
    const float* vg  = g_qkv + (size_t)(2 * Bq * T + b * T) * D;
    const float* hRs = hR + ((size_t)b * T * T + i) * D;
#pragma unroll
    for (int rep = 0; rep < 2; rep++) {
        int d = tid + rep * 256;
        if (d < D) {
            float acc = 0.f;
            for (int j = 0; j < T; j++) {
                float a = attn_s[j];
                if (a > 1e-12f)
                    acc += a * (vg[j * D + d] + hRs[(size_t)j * T * D + d]);
            }
            out[(b * T + i) * D + d] = acc;
        }
    }
}

// ---------------------------------------------------------------------------
extern "C" void kernel_launch(void* const* d_in, const int* in_sizes, int n_in,
                              void* d_out, int out_size)
{
    const float* query = (const float*)d_in[0];
    const float* key   = (const float*)d_in[1];
    const float* value = (const float*)d_in[2];
    const float* hL    = (const float*)d_in[3];
    const float* hR    = (const float*)d_in[4];
    const float* WQ    = (const float*)d_in[5];
    const float* bQ    = (const float*)d_in[6];
    const float* WK    = (const float*)d_in[7];
    const float* bK    = (const float*)d_in[8];
    float* out = (float*)d_out;

    // 1536 rows x 300 cols: 48 row tiles x 10 col tiles of 32 = 480 CTAs
    proj_kernel<<<dim3(10, 48), 128>>>(query, key, value, WQ, bQ, WK, bK);
    attn_kernel<<<Bq * T, 256>>>(hL, hR, out);
}

// round 10
// speedup vs baseline: 1.3481x; 1.1392x over previous
#include <cuda_runtime.h>
#include <cstdint>

#define Bq 4
#define T 128
#define D 300
#define D4 75            // D / 4 (float4 count per row)

// Scratch for projected q (rows 0..511), k (512..1023), v (1024..1535)
__device__ __align__(16) float g_qkv[3 * Bq * T * D];

// ---------------------------------------------------------------------------
// Kernel 1: batched projection GEMM. 32x32 tiles, 128 threads, 4x2 microtile,
// k-chunk 32, double-buffered. SWIZZLED smem layout: element [row][k] lives
// at [k][(row + (k & ~3)) & 31], stride 36. This makes the transposing STS
// conflict-free while keeping float4/float2 compute reads aligned and
// conflict-free, and global loads coalesced.
// out[r,c] = A[r,:] . W[c,:] + bias[c]
// rows 0..511 -> query/WQ/bQ, 512..1023 -> key/WK/bK, 1024..1535 -> value/WK/bK
// ---------------------------------------------------------------------------
__global__ __launch_bounds__(128) void proj_kernel(
    const float* __restrict__ query, const float* __restrict__ key,
    const float* __restrict__ value,
    const float* __restrict__ WQ, const float* __restrict__ bQ,
    const float* __restrict__ WK, const float* __restrict__ bK)
{
    __shared__ float A_s[2][32][36];
    __shared__ float W_s[2][32][36];

    const int row0 = blockIdx.y * 32;
    const int col0 = blockIdx.x * 32;
    const int tid  = threadIdx.x;
    const int tx   = tid & 15;    // 16 col groups x 2 cols
    const int ty   = tid >> 4;    // 8 row groups x 4 rows

    const int sel = row0 >> 9;    // 0: query, 1: key, 2: value
    const float* Ap = (sel == 0) ? query : (sel == 1 ? key : value);
    const float* Wp = (sel == 0) ? WQ : WK;
    const float* bp = (sel == 0) ? bQ : bK;
    const int arow0 = row0 & 511;

    // loader: coalesced float4 along k; each thread handles rows lm, lm+16
    const int lm = tid >> 3;          // 0..15
    const int lk = (tid & 7) * 4;     // 0,4,..,28

    const int NC = (D + 31) / 32;     // 10 chunks
    float4 a_r[2], w_r[2];

    auto fetch = [&](int k0) {
        bool kv = (k0 + lk) < D;      // D%4==0: float4 never straddles
#pragma unroll
        for (int p = 0; p < 2; p++) {
            int r = lm + p * 16;
            a_r[p] = kv ? *(const float4*)&Ap[(arow0 + r) * D + k0 + lk]
                        : make_float4(0.f, 0.f, 0.f, 0.f);
            int gc = col0 + r;
            w_r[p] = (kv && gc < D) ? *(const float4*)&Wp[gc * D + k0 + lk]
                                    : make_float4(0.f, 0.f, 0.f, 0.f);
        }
    };
    auto store = [&](int buf) {
#pragma unroll
        for (int p = 0; p < 2; p++) {
            int r   = lm + p * 16;
            int col = (r + lk) & 31;          // swizzle: same col for all 4 k
            A_s[buf][lk + 0][col] = a_r[p].x; A_s[buf][lk + 1][col] = a_r[p].y;
            A_s[buf][lk + 2][col] = a_r[p].z; A_s[buf][lk + 3][col] = a_r[p].w;
            W_s[buf][lk + 0][col] = w_r[p].x; W_s[buf][lk + 1][col] = w_r[p].y;
            W_s[buf][lk + 2][col] = w_r[p].z; W_s[buf][lk + 3][col] = w_r[p].w;
        }
    };

    float acc[4][2];
#pragma unroll
    for (int r = 0; r < 4; r++) { acc[r][0] = 0.f; acc[r][1] = 0.f; }

    fetch(0);
    store(0);
    __syncthreads();

    for (int ch = 0; ch < NC; ch++) {
        const int buf = ch & 1;
        if (ch + 1 < NC) fetch((ch + 1) * 32);
#pragma unroll
        for (int e = 0; e < 32; e++) {
            const int off = e & ~3;
            float4 av = *(const float4*)&A_s[buf][e][(ty * 4 + off) & 31];
            float2 wv = *(const float2*)&W_s[buf][e][(tx * 2 + off) & 31];
            acc[0][0] += av.x * wv.x; acc[0][1] += av.x * wv.y;
            acc[1][0] += av.y * wv.x; acc[1][1] += av.y * wv.y;
            acc[2][0] += av.z * wv.x; acc[2][1] += av.z * wv.y;
            acc[3][0] += av.w * wv.x; acc[3][1] += av.w * wv.y;
        }
        if (ch + 1 < NC) store(1 - buf);
        __syncthreads();
    }

#pragma unroll
    for (int r = 0; r < 4; r++) {
        int gr = row0 + ty * 4 + r;
#pragma unroll
        for (int c = 0; c < 2; c++) {
            int gcol = col0 + tx * 2 + c;
            if (gcol < D) g_qkv[gr * D + gcol] = acc[r][c] + bp[gcol];
        }
    }
}

// ---------------------------------------------------------------------------
// Kernel 2: fused attention — round-4 streaming core (proven 36us) plus a
// compacted significant-j list so the output phase touches only the ~1-4
// post-sharpening survivors instead of scanning all 128.
// ---------------------------------------------------------------------------
__global__ __launch_bounds__(256, 4) void attn_kernel(
    const float* __restrict__ hL, const float* __restrict__ hR,
    float* __restrict__ out)
{
    __shared__ float q_s[304];
    __shared__ float scores_s[128];
    __shared__ float listw_s[128];
    __shared__ int   listj_s[128];
    __shared__ int   cnt_s;

    const int tid  = threadIdx.x;
    const int lane = tid & 31;
    const int w    = tid >> 5;           // 8 warps
    const int b    = blockIdx.x >> 7;
    const int i    = blockIdx.x & 127;

    const float4* qkv4 = (const float4*)g_qkv;

    // ---- load q_i (L2-hot, tiny) ----
    if (tid < D4) ((float4*)q_s)[tid] = qkv4[(b * T + i) * D4 + tid];
    __syncthreads();

    const float4* q4 = (const float4*)q_s;
    const bool has_c = (lane < D4 - 64);           // lane < 11

    // ---- scoring: scores_j = sum_d (q[d]+hL[b,i,j,d]) * (k[b,j,d]+hR[b,j,i,d])
    const float4* hL4 = (const float4*)hL + (size_t)(b * T + i) * T * D4;
    const float4* hRb = (const float4*)hR + ((size_t)b * T * T + i) * D4;
    const float4* k4b = qkv4 + (Bq * T + b * T) * D4;

#pragma unroll 2
    for (int jj = 0; jj < 16; jj++) {
        const int j = w * 16 + jj;
        const float4* hl = hL4 + j * D4;
        const float4* hr = hRb + (size_t)j * T * D4;
        const float4* kp = k4b + j * D4;

        float4 l0 = hl[lane],      r0 = hr[lane],      k0 = kp[lane];
        float4 l1 = hl[lane + 32], r1 = hr[lane + 32], k1 = kp[lane + 32];
        float4 l2, r2, k2;
        if (has_c) { l2 = hl[lane + 64]; r2 = hr[lane + 64]; k2 = kp[lane + 64]; }

        float4 qa = q4[lane];
        float acc = (qa.x + l0.x) * (k0.x + r0.x) + (qa.y + l0.y) * (k0.y + r0.y)
                  + (qa.z + l0.z) * (k0.z + r0.z) + (qa.w + l0.w) * (k0.w + r0.w);
        float4 qb = q4[lane + 32];
        acc += (qb.x + l1.x) * (k1.x + r1.x) + (qb.y + l1.y) * (k1.y + r1.y)
             + (qb.z + l1.z) * (k1.z + r1.z) + (qb.w + l1.w) * (k1.w + r1.w);
        if (has_c) {
            float4 qc = q4[lane + 64];
            acc += (qc.x + l2.x) * (k2.x + r2.x) + (qc.y + l2.y) * (k2.y + r2.y)
                 + (qc.z + l2.z) * (k2.z + r2.z) + (qc.w + l2.w) * (k2.w + r2.w);
        }
#pragma unroll
        for (int o = 16; o > 0; o >>= 1)
            acc += __shfl_xor_sync(0xffffffffu, acc, o);
        if (lane == 0) scores_s[j] = acc;
    }
    __syncthreads();

    // ---- p = softmax(scores); attn = softmax(1000*p); clip is a no-op.
    // p_max = 1/sum exactly (max exp term is 1): 1000*(p-p_max) = 1000*inv*(e-1)
    // Then build an ORDERED compact list of significant j (deterministic).
    if (w == 0) {
        float s0 = scores_s[lane],      s1 = scores_s[lane + 32];
        float s2 = scores_s[lane + 64], s3 = scores_s[lane + 96];
        float m = fmaxf(fmaxf(s0, s1), fmaxf(s2, s3));
#pragma unroll
        for (int o = 16; o > 0; o >>= 1)
            m = fmaxf(m, __shfl_xor_sync(0xffffffffu, m, o));
        float e0 = expf(s0 - m), e1 = expf(s1 - m);
        float e2 = expf(s2 - m), e3 = expf(s3 - m);
        float sum = e0 + e1 + e2 + e3;
#pragma unroll
        for (int o = 16; o > 0; o >>= 1)
            sum += __shfl_xor_sync(0xffffffffu, sum, o);
        float inv = 1.f / sum;
        float a0 = expf(1000.f * inv * (e0 - 1.f));
        float a1 = expf(1000.f * inv * (e1 - 1.f));
        float a2 = expf(1000.f * inv * (e2 - 1.f));
        float a3 = expf(1000.f * inv * (e3 - 1.f));
        float sum2 = a0 + a1 + a2 + a3;
#pragma unroll
        for (int o = 16; o > 0; o >>= 1)
            sum2 += __shfl_xor_sync(0xffffffffu, sum2, o);
        float inv2 = 1.f / sum2;

        float av[4] = {a0 * inv2, a1 * inv2, a2 * inv2, a3 * inv2};
        int base = 0;
#pragma unroll
        for (int qd = 0; qd < 4; qd++) {
            bool f = av[qd] > 1e-12f;
            unsigned mask = __ballot_sync(0xffffffffu, f);
            int pos = base + __popc(mask & ((1u << lane) - 1u));
            if (f) { listj_s[pos] = qd * 32 + lane; listw_s[pos] = av[qd]; }
            base += __popc(mask);
        }
        if (lane == 0) cnt_s = base;
    }
    __syncthreads();

    // ---- output: out[b,i,d] = sum over significant j of a_j*(v[j,d]+hR[j,i,d])
    const float* vg  = g_qkv + (size_t)(2 * Bq * T + b * T) * D;
    const float* hRs = hR + ((size_t)b * T * T + i) * D;
    const int cnt = cnt_s;
#pragma unroll
    for (int rep = 0; rep < 2; rep++) {
        int d = tid + rep * 256;
        if (d < D) {
            float acc = 0.f;
            for (int t = 0; t < cnt; t++) {
                int   j = listj_s[t];
                float a = listw_s[t];
                acc += a * (vg[j * D + d] + hRs[(size_t)j * T * D + d]);
            }
            out[(b * T + i) * D + d] = acc;
        }
    }
}

// ---------------------------------------------------------------------------
extern "C" void kernel_launch(void* const* d_in, const int* in_sizes, int n_in,
                              void* d_out, int out_size)
{
    const float* query = (const float*)d_in[0];
    const float* key   = (const float*)d_in[1];
    const float* value = (const float*)d_in[2];
    const float* hL    = (const float*)d_in[3];
    const float* hR    = (const float*)d_in[4];
    const float* WQ    = (const float*)d_in[5];
    const float* bQ    = (const float*)d_in[6];
    const float* WK    = (const float*)d_in[7];
    const float* bK    = (const float*)d_in[8];
    float* out = (float*)d_out;

    // 1536 rows x 300 cols: 48 row tiles x 10 col tiles of 32 = 480 CTAs
    proj_kernel<<<dim3(10, 48), 128>>>(query, key, value, WQ, bQ, WK, bK);
    attn_kernel<<<Bq * T, 256>>>(hL, hR, out);
}